// round 1
// baseline (speedup 1.0000x reference)
#include <cuda_runtime.h>
#include <math.h>

#define SUB_NO 20
#define T_NO   201
#define E_NO   2000
#define I_NO   500
#define T_DATA 20000
#define NC     (E_NO + I_NO)     // 2500
#define NCOL   64                // padded GEMM columns (60 used: 3 variants x 20 subunits)
#define MT     128               // GEMM M tile
#define KC     20                // GEMM K tile

// ---------------- scratch (device globals; no allocation allowed) ----------------
__device__ float g_We[E_NO * NCOL];          // [k][n] weights for S_e
__device__ float g_Wi[I_NO * NCOL];          // [k][n] weights for S_i
__device__ float g_INTe0[NCOL * T_DATA];     // e-GEMM partial (K 0..999),  layout [col][t]
__device__ float g_INTe1[NCOL * T_DATA];     // e-GEMM partial (K 1000..1999)
__device__ float g_INTi [NCOL * T_DATA];     // i-GEMM,                     layout [col][t]
__device__ float g_kern[2 * SUB_NO * T_NO];  // [typ][s][tau]
__device__ int   g_L;                        // effective kernel length

// ---------------- kernel 0: temporal kernel taps + effective length ----------------
__global__ void kern_setup(const float* __restrict__ W_syn,
                           const float* __restrict__ Tau_syn,
                           const float* __restrict__ Delta_syn) {
    __shared__ int sh_l[256];
    int lmax = 1;
    for (int idx = threadIdx.x; idx < 2 * SUB_NO * T_NO; idx += blockDim.x) {
        int ch    = idx / T_NO;        // ch = s*2 + typ (matches row-major [s][typ])
        int tau_i = idx % T_NO;
        int s = ch >> 1, typ = ch & 1;
        float dly = expf(Delta_syn[ch]);
        float tt  = fmaxf((float)tau_i - dly, 0.0f) / expf(Tau_syn[ch]);
        float k   = tt * expf(-tt) * W_syn[ch];
        g_kern[typ * (SUB_NO * T_NO) + s * T_NO + tau_i] = k;
        if (fabsf(k) > 1e-12f) lmax = max(lmax, tau_i + 1);
    }
    sh_l[threadIdx.x] = lmax;
    __syncthreads();
    for (int off = 128; off > 0; off >>= 1) {
        if ((int)threadIdx.x < off)
            sh_l[threadIdx.x] = max(sh_l[threadIdx.x], sh_l[threadIdx.x + off]);
        __syncthreads();
    }
    if (threadIdx.x == 0) g_L = sh_l[0];
}

// ---------------- kernel 1: reparam stage + weight-matrix build ----------------
// One thread per column (2500 columns).
__global__ void kern_reparam(const float* __restrict__ u_in,
                             const float* __restrict__ v_in,
                             const float* __restrict__ C_log,
                             float* __restrict__ out) {
    int col = blockIdx.x * blockDim.x + threadIdx.x;
    if (col >= NC) return;

    float cl[SUB_NO], th[SUB_NO], rz[SUB_NO];
    float m = -INFINITY;
#pragma unroll
    for (int s = 0; s < SUB_NO; s++) { cl[s] = C_log[s * NC + col]; m = fmaxf(m, cl[s]); }
    float sum = 0.0f;
#pragma unroll
    for (int s = 0; s < SUB_NO; s++) { th[s] = expf(cl[s] - m); sum += th[s]; }
    float inv = 1.0f / sum;

    int   kidx = 0;
    float best = -INFINITY;
#pragma unroll
    for (int s = 0; s < SUB_NO; s++) {
        th[s] *= inv;
        float uu = u_in[s * NC + col];
        rz[s] = logf(th[s]) - logf(-logf(uu));
        if (rz[s] > best) { best = rz[s]; kidx = s; }   // first max, like jnp.argmax
    }
    float vk   = v_in[kidx * NC + col];
    float nlvk = -logf(vk);                              // -log(v_k) > 0

    float* W; int j;
    if (col < E_NO) { W = g_We; j = col; } else { W = g_Wi; j = col - E_NO; }

#pragma unroll
    for (int s = 0; s < SUB_NO; s++) {
        float hard = (s == kidx) ? 1.0f : 0.0f;
        float soft = 1.0f / (1.0f + expf(-2.0f * rz[s])) + 1e-9f;
        float vv   = v_in[s * NC + col];
        float nlv  = -logf(vv);
        float rzb  = (s == kidx) ? (-logf(nlv)) : (-logf(nlv / th[s] + nlvk));
        float szb  = 1.0f / (1.0f + expf(-2.0f * rzb)) + 1e-9f;

        // outputs: theta | hard | soft | softzb at offsets after 3 V vectors
        out[3 * T_DATA + 0 * SUB_NO * NC + s * NC + col] = th[s];
        out[3 * T_DATA + 1 * SUB_NO * NC + s * NC + col] = hard;
        out[3 * T_DATA + 2 * SUB_NO * NC + s * NC + col] = soft;
        out[3 * T_DATA + 3 * SUB_NO * NC + s * NC + col] = szb;

        // GEMM B matrix: col n = var*20 + s (var 0=hard,1=soft,2=softzb)
        W[j * NCOL + 0 * SUB_NO + s] = hard;
        W[j * NCOL + 1 * SUB_NO + s] = soft;
        W[j * NCOL + 2 * SUB_NO + s] = szb;
    }
    // zero padding columns 60..63
    W[j * NCOL + 60] = 0.0f; W[j * NCOL + 61] = 0.0f;
    W[j * NCOL + 62] = 0.0f; W[j * NCOL + 63] = 0.0f;
}

// ---------------- kernel 2: fused GEMMs ----------------
// grid 471: blocks [0,314): E-phase (157 M-tiles x 2 K-halves); [314,471): I-phase.
// Block: 256 threads, tile 128(M) x 64(N). Output layout [col][t] (for conv coalescing).
__global__ __launch_bounds__(256) void kern_gemm(const float* __restrict__ S_e,
                                                 const float* __restrict__ S_i) {
    __shared__ float Ssh[KC][MT + 4];        // transposed S tile
    __shared__ float Bsh[KC * NCOL];

    int bx = blockIdx.x;
    const float* S; const float* W; float* OUT;
    int ldS, kiters, t0;
    if (bx < 314) {
        int kh = bx & 1;
        int mt = bx >> 1;
        S = S_e + kh * 1000;                 // K-half column offset baked into pointer
        ldS = E_NO; kiters = 1000 / KC;
        W = g_We + kh * 1000 * NCOL;
        OUT = kh ? g_INTe1 : g_INTe0;
        t0 = mt * MT;
    } else {
        int mt = bx - 314;
        S = S_i; ldS = I_NO; kiters = I_NO / KC;
        W = g_Wi; OUT = g_INTi;
        t0 = mt * MT;
    }

    int tid  = threadIdx.x;
    int trow = tid >> 3;                     // 0..31 -> rows trow*4..+3
    int tcol = tid & 7;                      // 0..7  -> cols tcol*8..+7

    float acc[4][8];
#pragma unroll
    for (int r = 0; r < 4; r++)
#pragma unroll
        for (int c = 0; c < 8; c++) acc[r][c] = 0.0f;

    for (int kt = 0; kt < kiters; kt++) {
        int k0 = kt * KC;
        // B tile: contiguous copy (KC*NCOL floats)
        for (int i = tid; i < (KC * NCOL) / 4; i += 256)
            ((float4*)Bsh)[i] = ((const float4*)(W + k0 * NCOL))[i];
        // S tile, transposed into shared (k-fast over global for coalescing)
        for (int i = tid; i < KC * MT; i += 256) {
            int kk = i % KC;
            int r  = i / KC;
            int t  = t0 + r;
            Ssh[kk][r] = (t < T_DATA) ? S[(size_t)t * ldS + k0 + kk] : 0.0f;
        }
        __syncthreads();
#pragma unroll
        for (int kk = 0; kk < KC; kk++) {
            float4 a  = *(const float4*)&Ssh[kk][trow * 4];
            const float4* bp = (const float4*)&Bsh[kk * NCOL + tcol * 8];
            float4 b0 = bp[0], b1 = bp[1];
            float av[4] = {a.x, a.y, a.z, a.w};
            float bv[8] = {b0.x, b0.y, b0.z, b0.w, b1.x, b1.y, b1.z, b1.w};
#pragma unroll
            for (int r = 0; r < 4; r++)
#pragma unroll
                for (int c = 0; c < 8; c++)
                    acc[r][c] = fmaf(av[r], bv[c], acc[r][c]);
        }
        __syncthreads();
    }

    // write transposed output [col][t]; rows are 4 consecutive t -> STG.128
    int tb = t0 + trow * 4;
#pragma unroll
    for (int c = 0; c < 8; c++) {
        int colg = tcol * 8 + c;
        if (tb + 3 < T_DATA) {
            float4 o = make_float4(acc[0][c], acc[1][c], acc[2][c], acc[3][c]);
            *(float4*)&OUT[(size_t)colg * T_DATA + tb] = o;
        } else {
#pragma unroll
            for (int r = 0; r < 4; r++)
                if (tb + r < T_DATA) OUT[(size_t)colg * T_DATA + tb + r] = acc[r][c];
        }
    }
}

// ---------------- kernel 3: causal conv (truncated) + subunit tree ----------------
// grid 471 = 3 variants x 157 t-tiles of 128. 128 threads, 1 output t per thread.
#define CONV_STRIDE 328
#define SYN_STRIDE  21
__global__ __launch_bounds__(128) void kern_conv(const float* __restrict__ W_sub,
                                                 const float* __restrict__ V_o,
                                                 float* __restrict__ out) {
    extern __shared__ float sm[];
    float* es  = sm;                          // [20][328]  e inputs
    float* is_ = sm + SUB_NO * CONV_STRIDE;   // [20][328]  i inputs
    float* ksh = is_ + SUB_NO * CONV_STRIDE;  // [2*20][201] kernel taps
    float* syn = ksh + 2 * SUB_NO * T_NO;     // [128][21]   per-thread syn_in

    int bx = blockIdx.x;
    int v  = bx / 157;
    int mt = bx % 157;
    int t0 = mt * MT;
    int tid = threadIdx.x;

    int L      = g_L;
    int nrows  = MT + L - 1;
    int tbase  = t0 - (L - 1);

    // stage kernel taps
    for (int idx = tid; idx < 2 * SUB_NO * L; idx += 128) {
        int ch  = idx / L;         // typ*20+s
        int tau = idx % L;
        ksh[ch * T_NO + tau] = g_kern[ch * T_NO + tau];
    }
    // stage input tiles (coalesced along t; layout [s][j] conflict-free for compute)
    for (int s = 0; s < SUB_NO; s++) {
        int ce = (v * SUB_NO + s) * T_DATA;
        for (int j = tid; j < nrows; j += 128) {
            int t = tbase + j;
            float ev = 0.0f, iv = 0.0f;
            if (t >= 0 && t < T_DATA) {
                ev = g_INTe0[ce + t] + g_INTe1[ce + t];
                iv = g_INTi[ce + t];
            }
            es[s * CONV_STRIDE + j]  = ev;
            is_[s * CONV_STRIDE + j] = iv;
        }
    }
    __syncthreads();

    int i = tid;
    int t = t0 + i;

    // convolutions (single code copy; syn via padded shared to avoid local-mem array)
    for (int s = 0; s < SUB_NO; s++) {
        const float* ke = &ksh[s * T_NO];
        const float* ki = &ksh[(SUB_NO + s) * T_NO];
        int base = s * CONV_STRIDE + i + L - 1;
        float ae = 0.0f, ai = 0.0f;
#pragma unroll 4
        for (int tau = 0; tau < L; tau++) {
            ae = fmaf(ke[tau], es[base - tau], ae);
            ai = fmaf(ki[tau], is_[base - tau], ai);
        }
        syn[i * SYN_STRIDE + s] = ae + ai;
    }

    // binary tree: children of s are 2s+1, 2s+2 (if < 20); process 19 -> 0
    float ws[SUB_NO];
#pragma unroll
    for (int s = 0; s < SUB_NO; s++) ws[s] = __ldg(&W_sub[s]);

    float sub[SUB_NO];
#pragma unroll
    for (int ss = 0; ss < SUB_NO; ss++) {
        int s = SUB_NO - 1 - ss;
        float x = syn[i * SYN_STRIDE + s];
        if (2 * s + 1 < SUB_NO) x += sub[2 * s + 1] * ws[2 * s + 1];
        if (2 * s + 2 < SUB_NO) x += sub[2 * s + 2] * ws[2 * s + 2];
        sub[s] = tanhf(x);
    }
    if (t < T_DATA)
        out[v * T_DATA + t] = sub[0] * ws[0] + __ldg(&V_o[0]);
}

// ---------------- launcher ----------------
extern "C" void kernel_launch(void* const* d_in, const int* in_sizes, int n_in,
                              void* d_out, int out_size) {
    const float* S_e    = (const float*)d_in[0];
    const float* S_i    = (const float*)d_in[1];
    const float* u      = (const float*)d_in[2];
    const float* v      = (const float*)d_in[3];
    const float* W_syn  = (const float*)d_in[4];
    const float* Tau    = (const float*)d_in[5];
    const float* Delta  = (const float*)d_in[6];
    const float* W_sub  = (const float*)d_in[7];
    const float* V_o    = (const float*)d_in[8];
    // d_in[9] = Theta (unused by reference)
    const float* C_log  = (const float*)d_in[10];
    float* out = (float*)d_out;

    // conv kernel dynamic smem: tiles (2*20*328) + taps (2*20*201) + syn (128*21)
    static const int conv_smem =
        (2 * SUB_NO * CONV_STRIDE + 2 * SUB_NO * T_NO + 128 * SYN_STRIDE) * (int)sizeof(float);
    cudaFuncSetAttribute(kern_conv, cudaFuncAttributeMaxDynamicSharedMemorySize, conv_smem);

    kern_setup<<<1, 256>>>(W_syn, Tau, Delta);
    kern_reparam<<<(NC + 255) / 256, 256>>>(u, v, C_log, out);
    kern_gemm<<<471, 256>>>(S_e, S_i);
    kern_conv<<<471, 128, conv_smem>>>(W_sub, V_o, out);
}

// round 2
// speedup vs baseline: 1.0012x; 1.0012x over previous
#include <cuda_runtime.h>
#include <math.h>

#define SUB_NO 20
#define T_NO   201
#define E_NO   2000
#define I_NO   500
#define T_DATA 20000
#define NC     (E_NO + I_NO)     // 2500
#define NCOL   64                // padded GEMM columns (60 used: 3 variants x 20 subunits)
#define MT     128               // GEMM M tile
#define KC     20                // GEMM K tile

// ---------------- scratch (device globals; no allocation allowed) ----------------
__device__ float g_We[E_NO * NCOL];          // [k][n] weights for S_e
__device__ float g_Wi[I_NO * NCOL];          // [k][n] weights for S_i
__device__ float g_INTe0[NCOL * T_DATA];     // e-GEMM partial (K 0..999),  layout [col][t]
__device__ float g_INTe1[NCOL * T_DATA];     // e-GEMM partial (K 1000..1999)
__device__ float g_INTi [NCOL * T_DATA];     // i-GEMM,                     layout [col][t]
__device__ float g_kern[2 * SUB_NO * T_NO];  // [typ][s][tau]
__device__ int   g_L;                        // effective kernel length

// ---------------- kernel 0: temporal kernel taps + effective length ----------------
__global__ void kern_setup(const float* __restrict__ W_syn,
                           const float* __restrict__ Tau_syn,
                           const float* __restrict__ Delta_syn) {
    __shared__ int sh_l[256];
    int lmax = 1;
    for (int idx = threadIdx.x; idx < 2 * SUB_NO * T_NO; idx += blockDim.x) {
        int ch    = idx / T_NO;        // ch = s*2 + typ (matches row-major [s][typ])
        int tau_i = idx % T_NO;
        int s = ch >> 1, typ = ch & 1;
        float dly = expf(Delta_syn[ch]);
        float tt  = fmaxf((float)tau_i - dly, 0.0f) / expf(Tau_syn[ch]);
        float k   = tt * expf(-tt) * W_syn[ch];
        g_kern[typ * (SUB_NO * T_NO) + s * T_NO + tau_i] = k;
        if (fabsf(k) > 1e-12f) lmax = max(lmax, tau_i + 1);
    }
    sh_l[threadIdx.x] = lmax;
    __syncthreads();
    for (int off = 128; off > 0; off >>= 1) {
        if ((int)threadIdx.x < off)
            sh_l[threadIdx.x] = max(sh_l[threadIdx.x], sh_l[threadIdx.x + off]);
        __syncthreads();
    }
    if (threadIdx.x == 0) g_L = sh_l[0];
}

// ---------------- kernel 1: reparam stage + weight-matrix build ----------------
// One thread per column (2500 columns).
__global__ void kern_reparam(const float* __restrict__ u_in,
                             const float* __restrict__ v_in,
                             const float* __restrict__ C_log,
                             float* __restrict__ out) {
    int col = blockIdx.x * blockDim.x + threadIdx.x;
    if (col >= NC) return;

    float cl[SUB_NO], th[SUB_NO], rz[SUB_NO];
    float m = -INFINITY;
#pragma unroll
    for (int s = 0; s < SUB_NO; s++) { cl[s] = C_log[s * NC + col]; m = fmaxf(m, cl[s]); }
    float sum = 0.0f;
#pragma unroll
    for (int s = 0; s < SUB_NO; s++) { th[s] = expf(cl[s] - m); sum += th[s]; }
    float inv = 1.0f / sum;

    int   kidx = 0;
    float best = -INFINITY;
#pragma unroll
    for (int s = 0; s < SUB_NO; s++) {
        th[s] *= inv;
        float uu = u_in[s * NC + col];
        rz[s] = logf(th[s]) - logf(-logf(uu));
        if (rz[s] > best) { best = rz[s]; kidx = s; }   // first max, like jnp.argmax
    }
    float vk   = v_in[kidx * NC + col];
    float nlvk = -logf(vk);                              // -log(v_k) > 0

    float* W; int j;
    if (col < E_NO) { W = g_We; j = col; } else { W = g_Wi; j = col - E_NO; }

#pragma unroll
    for (int s = 0; s < SUB_NO; s++) {
        float hard = (s == kidx) ? 1.0f : 0.0f;
        float soft = 1.0f / (1.0f + expf(-2.0f * rz[s])) + 1e-9f;
        float vv   = v_in[s * NC + col];
        float nlv  = -logf(vv);
        float rzb  = (s == kidx) ? (-logf(nlv)) : (-logf(nlv / th[s] + nlvk));
        float szb  = 1.0f / (1.0f + expf(-2.0f * rzb)) + 1e-9f;

        // outputs: theta | hard | soft | softzb at offsets after 3 V vectors
        out[3 * T_DATA + 0 * SUB_NO * NC + s * NC + col] = th[s];
        out[3 * T_DATA + 1 * SUB_NO * NC + s * NC + col] = hard;
        out[3 * T_DATA + 2 * SUB_NO * NC + s * NC + col] = soft;
        out[3 * T_DATA + 3 * SUB_NO * NC + s * NC + col] = szb;

        // GEMM B matrix: col n = var*20 + s (var 0=hard,1=soft,2=softzb)
        W[j * NCOL + 0 * SUB_NO + s] = hard;
        W[j * NCOL + 1 * SUB_NO + s] = soft;
        W[j * NCOL + 2 * SUB_NO + s] = szb;
    }
    // zero padding columns 60..63
    W[j * NCOL + 60] = 0.0f; W[j * NCOL + 61] = 0.0f;
    W[j * NCOL + 62] = 0.0f; W[j * NCOL + 63] = 0.0f;
}

// ---------------- kernel 2: fused GEMMs ----------------
// grid 471: blocks [0,314): E-phase (157 M-tiles x 2 K-halves); [314,471): I-phase.
// Block: 256 threads, tile 128(M) x 64(N). Output layout [col][t] (for conv coalescing).
__global__ __launch_bounds__(256) void kern_gemm(const float* __restrict__ S_e,
                                                 const float* __restrict__ S_i) {
    __shared__ float Ssh[KC][MT + 4];        // transposed S tile
    __shared__ float Bsh[KC * NCOL];

    int bx = blockIdx.x;
    const float* S; const float* W; float* OUT;
    int ldS, kiters, t0;
    if (bx < 314) {
        int kh = bx & 1;
        int mt = bx >> 1;
        S = S_e + kh * 1000;                 // K-half column offset baked into pointer
        ldS = E_NO; kiters = 1000 / KC;
        W = g_We + kh * 1000 * NCOL;
        OUT = kh ? g_INTe1 : g_INTe0;
        t0 = mt * MT;
    } else {
        int mt = bx - 314;
        S = S_i; ldS = I_NO; kiters = I_NO / KC;
        W = g_Wi; OUT = g_INTi;
        t0 = mt * MT;
    }

    int tid  = threadIdx.x;
    int trow = tid >> 3;                     // 0..31 -> rows trow*4..+3
    int tcol = tid & 7;                      // 0..7  -> cols tcol*8..+7

    float acc[4][8];
#pragma unroll
    for (int r = 0; r < 4; r++)
#pragma unroll
        for (int c = 0; c < 8; c++) acc[r][c] = 0.0f;

    for (int kt = 0; kt < kiters; kt++) {
        int k0 = kt * KC;
        // B tile: contiguous copy (KC*NCOL floats)
        for (int i = tid; i < (KC * NCOL) / 4; i += 256)
            ((float4*)Bsh)[i] = ((const float4*)(W + k0 * NCOL))[i];
        // S tile, transposed into shared (k-fast over global for coalescing)
        for (int i = tid; i < KC * MT; i += 256) {
            int kk = i % KC;
            int r  = i / KC;
            int t  = t0 + r;
            Ssh[kk][r] = (t < T_DATA) ? S[(size_t)t * ldS + k0 + kk] : 0.0f;
        }
        __syncthreads();
#pragma unroll
        for (int kk = 0; kk < KC; kk++) {
            float4 a  = *(const float4*)&Ssh[kk][trow * 4];
            const float4* bp = (const float4*)&Bsh[kk * NCOL + tcol * 8];
            float4 b0 = bp[0], b1 = bp[1];
            float av[4] = {a.x, a.y, a.z, a.w};
            float bv[8] = {b0.x, b0.y, b0.z, b0.w, b1.x, b1.y, b1.z, b1.w};
#pragma unroll
            for (int r = 0; r < 4; r++)
#pragma unroll
                for (int c = 0; c < 8; c++)
                    acc[r][c] = fmaf(av[r], bv[c], acc[r][c]);
        }
        __syncthreads();
    }

    // write transposed output [col][t]; rows are 4 consecutive t -> STG.128
    int tb = t0 + trow * 4;
#pragma unroll
    for (int c = 0; c < 8; c++) {
        int colg = tcol * 8 + c;
        if (tb + 3 < T_DATA) {
            float4 o = make_float4(acc[0][c], acc[1][c], acc[2][c], acc[3][c]);
            *(float4*)&OUT[(size_t)colg * T_DATA + tb] = o;
        } else {
#pragma unroll
            for (int r = 0; r < 4; r++)
                if (tb + r < T_DATA) OUT[(size_t)colg * T_DATA + tb + r] = acc[r][c];
        }
    }
}

// ---------------- kernel 3: causal conv (truncated) + subunit tree ----------------
// grid 471 = 3 variants x 157 t-tiles of 128. 128 threads, 1 output t per thread.
#define CONV_STRIDE 328
#define SYN_STRIDE  21
__global__ __launch_bounds__(128) void kern_conv(const float* __restrict__ W_sub,
                                                 const float* __restrict__ V_o,
                                                 float* __restrict__ out) {
    extern __shared__ float sm[];
    float* es  = sm;                          // [20][328]  e inputs
    float* is_ = sm + SUB_NO * CONV_STRIDE;   // [20][328]  i inputs
    float* ksh = is_ + SUB_NO * CONV_STRIDE;  // [2*20][201] kernel taps
    float* syn = ksh + 2 * SUB_NO * T_NO;     // [128][21]   per-thread syn_in

    int bx = blockIdx.x;
    int v  = bx / 157;
    int mt = bx % 157;
    int t0 = mt * MT;
    int tid = threadIdx.x;

    int L      = g_L;
    int nrows  = MT + L - 1;
    int tbase  = t0 - (L - 1);

    // stage kernel taps
    for (int idx = tid; idx < 2 * SUB_NO * L; idx += 128) {
        int ch  = idx / L;         // typ*20+s
        int tau = idx % L;
        ksh[ch * T_NO + tau] = g_kern[ch * T_NO + tau];
    }
    // stage input tiles (coalesced along t; layout [s][j] conflict-free for compute)
    for (int s = 0; s < SUB_NO; s++) {
        int ce = (v * SUB_NO + s) * T_DATA;
        for (int j = tid; j < nrows; j += 128) {
            int t = tbase + j;
            float ev = 0.0f, iv = 0.0f;
            if (t >= 0 && t < T_DATA) {
                ev = g_INTe0[ce + t] + g_INTe1[ce + t];
                iv = g_INTi[ce + t];
            }
            es[s * CONV_STRIDE + j]  = ev;
            is_[s * CONV_STRIDE + j] = iv;
        }
    }
    __syncthreads();

    int i = tid;
    int t = t0 + i;

    // convolutions (single code copy; syn via padded shared to avoid local-mem array)
    for (int s = 0; s < SUB_NO; s++) {
        const float* ke = &ksh[s * T_NO];
        const float* ki = &ksh[(SUB_NO + s) * T_NO];
        int base = s * CONV_STRIDE + i + L - 1;
        float ae = 0.0f, ai = 0.0f;
#pragma unroll 4
        for (int tau = 0; tau < L; tau++) {
            ae = fmaf(ke[tau], es[base - tau], ae);
            ai = fmaf(ki[tau], is_[base - tau], ai);
        }
        syn[i * SYN_STRIDE + s] = ae + ai;
    }

    // binary tree: children of s are 2s+1, 2s+2 (if < 20); process 19 -> 0
    float ws[SUB_NO];
#pragma unroll
    for (int s = 0; s < SUB_NO; s++) ws[s] = __ldg(&W_sub[s]);

    float sub[SUB_NO];
#pragma unroll
    for (int ss = 0; ss < SUB_NO; ss++) {
        int s = SUB_NO - 1 - ss;
        float x = syn[i * SYN_STRIDE + s];
        if (2 * s + 1 < SUB_NO) x += sub[2 * s + 1] * ws[2 * s + 1];
        if (2 * s + 2 < SUB_NO) x += sub[2 * s + 2] * ws[2 * s + 2];
        sub[s] = tanhf(x);
    }
    if (t < T_DATA)
        out[v * T_DATA + t] = sub[0] * ws[0] + __ldg(&V_o[0]);
}

// ---------------- launcher ----------------
extern "C" void kernel_launch(void* const* d_in, const int* in_sizes, int n_in,
                              void* d_out, int out_size) {
    const float* S_e    = (const float*)d_in[0];
    const float* S_i    = (const float*)d_in[1];
    const float* u      = (const float*)d_in[2];
    const float* v      = (const float*)d_in[3];
    const float* W_syn  = (const float*)d_in[4];
    const float* Tau    = (const float*)d_in[5];
    const float* Delta  = (const float*)d_in[6];
    const float* W_sub  = (const float*)d_in[7];
    const float* V_o    = (const float*)d_in[8];
    // d_in[9] = Theta (unused by reference)
    const float* C_log  = (const float*)d_in[10];
    float* out = (float*)d_out;

    // conv kernel dynamic smem: tiles (2*20*328) + taps (2*20*201) + syn (128*21)
    static const int conv_smem =
        (2 * SUB_NO * CONV_STRIDE + 2 * SUB_NO * T_NO + 128 * SYN_STRIDE) * (int)sizeof(float);
    cudaFuncSetAttribute(kern_conv, cudaFuncAttributeMaxDynamicSharedMemorySize, conv_smem);

    kern_setup<<<1, 256>>>(W_syn, Tau, Delta);
    kern_reparam<<<(NC + 255) / 256, 256>>>(u, v, C_log, out);
    kern_gemm<<<471, 256>>>(S_e, S_i);
    kern_conv<<<471, 128, conv_smem>>>(W_sub, V_o, out);
}

// round 4
// speedup vs baseline: 1.6408x; 1.6388x over previous
#include <cuda_runtime.h>
#include <cuda_bf16.h>
#include <math.h>
#include <stdint.h>

#define SUB_NO 20
#define T_NO   201
#define E_NO   2000
#define I_NO   500
#define T_DATA 20000
#define NC     2500
#define NCHUNK 40
#define MT     128

// ---------------- scratch globals ----------------
__device__ __nv_bfloat16 g_WbT[NCHUNK * 8192];  // pre-swizzled B tiles [chunk][128n x 64k]
__device__ float g_INTe[64 * T_DATA];           // e GEMM out [col][t], col=var*20+s
__device__ float g_INTi[64 * T_DATA];           // i GEMM out
__device__ float g_syn [60 * T_DATA];           // conv out per (var,sub)
__device__ float g_kern[2 * SUB_NO * T_NO];
__device__ int   g_L;

__device__ __forceinline__ uint32_t smem_u32(const void* p) {
    uint32_t a;
    asm("{ .reg .u64 t; cvta.to.shared.u64 t, %1; cvt.u32.u64 %0, t; }" : "=r"(a) : "l"(p));
    return a;
}
__device__ __forceinline__ void ldsm4(uint32_t* r, uint32_t addr) {
    asm volatile("ldmatrix.sync.aligned.m8n8.x4.shared.b16 {%0,%1,%2,%3}, [%4];"
                 : "=r"(r[0]), "=r"(r[1]), "=r"(r[2]), "=r"(r[3]) : "r"(addr));
}
__device__ __forceinline__ void mma16816(float* d, const uint32_t* a, const uint32_t* b) {
    asm volatile("mma.sync.aligned.m16n8k16.row.col.f32.bf16.bf16.f32 "
                 "{%0,%1,%2,%3}, {%4,%5,%6,%7}, {%8,%9}, {%0,%1,%2,%3};"
                 : "+f"(d[0]), "+f"(d[1]), "+f"(d[2]), "+f"(d[3])
                 : "r"(a[0]), "r"(a[1]), "r"(a[2]), "r"(a[3]), "r"(b[0]), "r"(b[1]));
}

// ---------------- kernel 0: taps + effective length ----------------
__global__ void kern_setup(const float* __restrict__ W_syn, const float* __restrict__ Tau_syn,
                           const float* __restrict__ Delta_syn) {
    __shared__ int sh_l[256];
    int lmax = 1;
    for (int idx = threadIdx.x; idx < 2 * SUB_NO * T_NO; idx += blockDim.x) {
        int ch = idx / T_NO, tau_i = idx % T_NO;
        int s = ch >> 1, typ = ch & 1;
        float dly = expf(Delta_syn[ch]);
        float tt  = fmaxf((float)tau_i - dly, 0.0f) / expf(Tau_syn[ch]);
        float k   = tt * expf(-tt) * W_syn[ch];
        g_kern[typ * (SUB_NO * T_NO) + s * T_NO + tau_i] = k;
        if (fabsf(k) > 1e-12f) lmax = max(lmax, tau_i + 1);
    }
    sh_l[threadIdx.x] = lmax;
    __syncthreads();
    for (int off = 128; off > 0; off >>= 1) {
        if ((int)threadIdx.x < off)
            sh_l[threadIdx.x] = max(sh_l[threadIdx.x], sh_l[threadIdx.x + off]);
        __syncthreads();
    }
    if (threadIdx.x == 0) g_L = sh_l[0];
}

// ---------------- kernel 1: reparam + bf16 B tiles ----------------
__global__ void kern_reparam(const float* __restrict__ u_in, const float* __restrict__ v_in,
                             const float* __restrict__ C_log, float* __restrict__ out) {
    int col = blockIdx.x * blockDim.x + threadIdx.x;
    if (col >= NC) return;
    float cl[SUB_NO], th[SUB_NO], rz[SUB_NO];
    float m = -INFINITY;
#pragma unroll
    for (int s = 0; s < SUB_NO; s++) { cl[s] = C_log[s * NC + col]; m = fmaxf(m, cl[s]); }
    float sum = 0.0f;
#pragma unroll
    for (int s = 0; s < SUB_NO; s++) { th[s] = expf(cl[s] - m); sum += th[s]; }
    float inv = 1.0f / sum;
    int kidx = 0; float best = -INFINITY;
#pragma unroll
    for (int s = 0; s < SUB_NO; s++) {
        th[s] *= inv;
        float uu = u_in[s * NC + col];
        rz[s] = logf(th[s]) - logf(-logf(uu));
        if (rz[s] > best) { best = rz[s]; kidx = s; }
    }
    float nlvk = -logf(v_in[kidx * NC + col]);

    int chunk = col >> 6, kk = col & 63;
    __nv_bfloat16* tile = g_WbT + (size_t)chunk * 8192;
    int nbase = (col < E_NO) ? 0 : 64;

#pragma unroll
    for (int s = 0; s < SUB_NO; s++) {
        float hard = (s == kidx) ? 1.0f : 0.0f;
        float soft = 1.0f / (1.0f + expf(-2.0f * rz[s])) + 1e-9f;
        float nlv  = -logf(v_in[s * NC + col]);
        float rzb  = (s == kidx) ? (-logf(nlv)) : (-logf(nlv / th[s] + nlvk));
        float szb  = 1.0f / (1.0f + expf(-2.0f * rzb)) + 1e-9f;

        out[3 * T_DATA + 0 * SUB_NO * NC + s * NC + col] = th[s];
        out[3 * T_DATA + 1 * SUB_NO * NC + s * NC + col] = hard;
        out[3 * T_DATA + 2 * SUB_NO * NC + s * NC + col] = soft;
        out[3 * T_DATA + 3 * SUB_NO * NC + s * NC + col] = szb;

        float w3[3] = {hard, soft, szb};
#pragma unroll
        for (int var = 0; var < 3; var++) {
            uint32_t off = (uint32_t)((nbase + var * SUB_NO + s) * 128 + kk * 2);
            off ^= (off >> 3) & 0x70;
            tile[off >> 1] = __float2bfloat16_rn(w3[var]);
        }
    }
}

// ---------------- kernel 2: fused bf16 HMMA GEMM ----------------
// Block 128(M)x128(N), 256 thr = 8 warps (4M x 2N), warp tile 32x64.
// N cols 0-59: e-side vars; 64-123: i-side (warp wn picks output buffer).
__global__ __launch_bounds__(256) void kern_gemm(const float* __restrict__ S_e,
                                                 const float* __restrict__ S_i) {
    __shared__ __align__(1024) char As[16384];   // 128 rows x 128B (64 bf16), SW128
    __shared__ __align__(1024) char Bs[16384];   // 128 n-rows x 128B, SW128

    int tid  = threadIdx.x;
    int lane = tid & 31, warp = tid >> 5;
    int wm   = warp & 3, wn = warp >> 2;
    int t0   = blockIdx.x * MT;

    uint32_t AsU = smem_u32(As), BsU = smem_u32(Bs);

    float acc[2][8][4];
#pragma unroll
    for (int ma = 0; ma < 2; ma++)
#pragma unroll
        for (int na = 0; na < 8; na++)
#pragma unroll
            for (int q = 0; q < 4; q++) acc[ma][na][q] = 0.0f;

    // per-lane ldmatrix address components (within-tile row/byte)
    int aRow = wm * 32 + (lane & 15);
    int aByt = (lane >> 4) << 4;
    int bRow = wn * 64 + (lane & 7) + ((lane >> 4) << 3);
    int bByt = ((lane >> 3) & 1) << 4;
    uint32_t aAddr0 = AsU + (uint32_t)aRow * 128 + (uint32_t)(aByt ^ ((aRow & 7) << 4));
    uint32_t bAddr0 = BsU + (uint32_t)bRow * 128 + (uint32_t)(bByt ^ ((bRow & 7) << 4));

    for (int c = 0; c < NCHUNK; c++) {
        // B tile: contiguous 16KB copy (pre-swizzled)
        const uint4* bs = (const uint4*)(g_WbT + (size_t)c * 8192);
        uint4* bd = (uint4*)Bs;
#pragma unroll
        for (int j = 0; j < 4; j++) bd[tid + (j << 8)] = bs[tid + (j << 8)];

        // A tile: 128 rows x 64 k fp32 -> bf16, swizzled store
        int kc0 = c << 6;
#pragma unroll
        for (int j = 0; j < 8; j++) {
            int idx = tid + (j << 8);
            int r = idx >> 4, q = idx & 15;
            int t = t0 + r, k = kc0 + (q << 2);
            float4 val = make_float4(0.f, 0.f, 0.f, 0.f);
            if (t < T_DATA && k < NC)
                val = (k < E_NO) ? *(const float4*)(S_e + (size_t)t * E_NO + k)
                                 : *(const float4*)(S_i + (size_t)t * I_NO + (k - E_NO));
            uint32_t lo, hi;
            asm("cvt.rn.bf16x2.f32 %0, %1, %2;" : "=r"(lo) : "f"(val.y), "f"(val.x));
            asm("cvt.rn.bf16x2.f32 %0, %1, %2;" : "=r"(hi) : "f"(val.w), "f"(val.z));
            uint32_t off = (uint32_t)((r << 7) + (q << 3));
            off ^= (off >> 3) & 0x70;
            *(uint2*)(As + off) = make_uint2(lo, hi);
        }
        __syncthreads();

#pragma unroll
        for (int ks = 0; ks < 4; ks++) {
            // swizzle-safe: ks*32 only toggles bits 5-6; XOR pattern uses bits 4-6 of byte
            uint32_t a[2][4], bf[16];
#pragma unroll
            for (int ma = 0; ma < 2; ma++) {
                int byt = (ks << 5) + aByt;
                int row = aRow + ma * 16;
                uint32_t ad = AsU + (uint32_t)row * 128 + (uint32_t)(byt ^ ((row & 7) << 4));
                ldsm4(a[ma], ad);
            }
#pragma unroll
            for (int p = 0; p < 4; p++) {
                int byt = (ks << 5) + bByt;
                int row = bRow + p * 16;
                uint32_t bd2 = BsU + (uint32_t)row * 128 + (uint32_t)(byt ^ ((row & 7) << 4));
                ldsm4(&bf[p * 4], bd2);
            }
#pragma unroll
            for (int ma = 0; ma < 2; ma++)
#pragma unroll
                for (int na = 0; na < 8; na++)
                    mma16816(acc[ma][na], a[ma], &bf[na * 2]);
        }
        __syncthreads();
    }

    // epilogue: direct stores to [col][t]
    float* base = (wn == 0) ? g_INTe : g_INTi;
#pragma unroll
    for (int ma = 0; ma < 2; ma++) {
        int t_lo = t0 + wm * 32 + ma * 16 + (lane >> 2);
        int t_hi = t_lo + 8;
#pragma unroll
        for (int na = 0; na < 8; na++) {
            int c0 = na * 8 + (lane & 3) * 2;
            float* p0 = base + (size_t)c0 * T_DATA;
            float* p1 = base + (size_t)(c0 + 1) * T_DATA;
            if (t_lo < T_DATA) { p0[t_lo] = acc[ma][na][0]; p1[t_lo] = acc[ma][na][1]; }
            if (t_hi < T_DATA) { p0[t_hi] = acc[ma][na][2]; p1[t_hi] = acc[ma][na][3]; }
        }
    }
}

// ---------------- kernel 3: truncated causal conv, 8 outputs/thread ----------------
#define CT    2048
#define CSLOT 284
__global__ __launch_bounds__(256) void kern_conv() {
    __shared__ float ke[208], ki[208];
    __shared__ float es[8 * CSLOT + 8], is_[8 * CSLOT + 8];

    int bx = blockIdx.x;
    int sid = bx % 60, tile = bx / 60;
    int t0 = tile * CT, s = sid % 20, tid = threadIdx.x;

    int L = (g_L + 7) & ~7;
    if (L > 208) L = 208;
    int nrows = CT + L - 1;

    for (int tau = tid; tau < L; tau += 256) {
        ke[tau] = (tau < T_NO) ? g_kern[s * T_NO + tau] : 0.0f;
        ki[tau] = (tau < T_NO) ? g_kern[SUB_NO * T_NO + s * T_NO + tau] : 0.0f;
    }
    const float* ge = g_INTe + (size_t)sid * T_DATA;
    const float* gi = g_INTi + (size_t)sid * T_DATA;
    float* esb = es + 8;
    float* isb = is_ + 8;
    int tb = t0 - (L - 1);
    for (int j = tid; j < nrows; j += 256) {
        int t = tb + j;
        float ev = 0.0f, iv = 0.0f;
        if (t >= 0 && t < T_DATA) { ev = ge[t]; iv = gi[t]; }
        int a = (j & 7) * CSLOT + (j >> 3);
        esb[a] = ev; isb[a] = iv;
    }
    __syncthreads();

    int p0 = tid * 8 + L - 1;
    float ae[8], ai[8], ew[8], iw[8];
#pragma unroll
    for (int r = 0; r < 8; r++) {
        ae[r] = 0.0f; ai[r] = 0.0f;
        int j = p0 + r;
        int a = (j & 7) * CSLOT + (j >> 3);
        ew[r] = esb[a]; iw[r] = isb[a];
    }
    int nblk = L >> 3;
    for (int tbk = 0; tbk < nblk; tbk++) {
#pragma unroll
        for (int tu = 0; tu < 8; tu++) {
            int tau = tbk * 8 + tu;
            float fe = ke[tau], fi = ki[tau];
#pragma unroll
            for (int r = 0; r < 8; r++) {
                ae[r] = fmaf(fe, ew[r], ae[r]);
                ai[r] = fmaf(fi, iw[r], ai[r]);
            }
            int j = p0 - tau - 1;
            int a = (j & 7) * CSLOT + (j >> 3);
#pragma unroll
            for (int r = 7; r > 0; r--) { ew[r] = ew[r - 1]; iw[r] = iw[r - 1]; }
            ew[0] = esb[a]; iw[0] = isb[a];
        }
    }

    float* so = g_syn + (size_t)sid * T_DATA;
    int tt = t0 + tid * 8;
    if (tt + 7 < T_DATA) {
        *(float4*)(so + tt)     = make_float4(ae[0]+ai[0], ae[1]+ai[1], ae[2]+ai[2], ae[3]+ai[3]);
        *(float4*)(so + tt + 4) = make_float4(ae[4]+ai[4], ae[5]+ai[5], ae[6]+ai[6], ae[7]+ai[7]);
    } else {
#pragma unroll
        for (int r = 0; r < 8; r++)
            if (tt + r < T_DATA) so[tt + r] = ae[r] + ai[r];
    }
}

// ---------------- kernel 4: subunit tree ----------------
__global__ __launch_bounds__(256) void kern_tree(const float* __restrict__ W_sub,
                                                 const float* __restrict__ V_o,
                                                 float* __restrict__ out) {
    int idx = blockIdx.x * blockDim.x + threadIdx.x;
    if (idx >= 3 * T_DATA) return;
    int v = idx / T_DATA, t = idx - v * T_DATA;

    float ws[SUB_NO];
#pragma unroll
    for (int s = 0; s < SUB_NO; s++) ws[s] = __ldg(&W_sub[s]);

    const float* sy = g_syn + (size_t)v * SUB_NO * T_DATA + t;
    float sub[SUB_NO];
#pragma unroll
    for (int ss = 0; ss < SUB_NO; ss++) {
        int s = SUB_NO - 1 - ss;
        float x = sy[(size_t)s * T_DATA];
        if (2 * s + 1 < SUB_NO) x += sub[2 * s + 1] * ws[2 * s + 1];
        if (2 * s + 2 < SUB_NO) x += sub[2 * s + 2] * ws[2 * s + 2];
        sub[s] = tanhf(x);
    }
    out[idx] = sub[0] * ws[0] + __ldg(&V_o[0]);
}

// ---------------- launcher ----------------
extern "C" void kernel_launch(void* const* d_in, const int* in_sizes, int n_in,
                              void* d_out, int out_size) {
    const float* S_e   = (const float*)d_in[0];
    const float* S_i   = (const float*)d_in[1];
    const float* u     = (const float*)d_in[2];
    const float* v     = (const float*)d_in[3];
    const float* W_syn = (const float*)d_in[4];
    const float* Tau   = (const float*)d_in[5];
    const float* Delta = (const float*)d_in[6];
    const float* W_sub = (const float*)d_in[7];
    const float* V_o   = (const float*)d_in[8];
    const float* C_log = (const float*)d_in[10];
    float* out = (float*)d_out;

    kern_setup<<<1, 256>>>(W_syn, Tau, Delta);
    kern_reparam<<<(NC + 255) / 256, 256>>>(u, v, C_log, out);
    kern_gemm<<<157, 256>>>(S_e, S_i);
    kern_conv<<<600, 256>>>();
    kern_tree<<<(3 * T_DATA + 255) / 256, 256>>>(W_sub, V_o, out);
}

// round 5
// speedup vs baseline: 3.3245x; 2.0262x over previous
#include <cuda_runtime.h>
#include <cuda_bf16.h>
#include <math.h>
#include <stdint.h>

#define SUB_NO 20
#define T_NO   201
#define E_NO   2000
#define I_NO   500
#define T_DATA 20000
#define NC     2500
#define NCHUNK 40
#define MT     64

// ---------------- scratch globals ----------------
__device__ __nv_bfloat16 g_WbT[NCHUNK * 8192];  // pre-swizzled B tiles [chunk][128n x 64k]
__device__ float g_INTe[64 * T_DATA];           // e GEMM out [col][t], col=var*20+s
__device__ float g_INTi[64 * T_DATA];           // i GEMM out
__device__ float g_syn [60 * T_DATA];           // conv out per (var,sub)
__device__ float g_kern[2 * SUB_NO * T_NO];
__device__ int   g_L;

__device__ __forceinline__ uint32_t smem_u32(const void* p) {
    uint32_t a;
    asm("{ .reg .u64 t; cvta.to.shared.u64 t, %1; cvt.u32.u64 %0, t; }" : "=r"(a) : "l"(p));
    return a;
}
__device__ __forceinline__ void ldsm4(uint32_t* r, uint32_t addr) {
    asm volatile("ldmatrix.sync.aligned.m8n8.x4.shared.b16 {%0,%1,%2,%3}, [%4];"
                 : "=r"(r[0]), "=r"(r[1]), "=r"(r[2]), "=r"(r[3]) : "r"(addr));
}
__device__ __forceinline__ void mma16816(float* d, const uint32_t* a, const uint32_t* b) {
    asm volatile("mma.sync.aligned.m16n8k16.row.col.f32.bf16.bf16.f32 "
                 "{%0,%1,%2,%3}, {%4,%5,%6,%7}, {%8,%9}, {%0,%1,%2,%3};"
                 : "+f"(d[0]), "+f"(d[1]), "+f"(d[2]), "+f"(d[3])
                 : "r"(a[0]), "r"(a[1]), "r"(a[2]), "r"(a[3]), "r"(b[0]), "r"(b[1]));
}

// ---------------- kernel 0: taps + effective length ----------------
__global__ void kern_setup(const float* __restrict__ W_syn, const float* __restrict__ Tau_syn,
                           const float* __restrict__ Delta_syn) {
    __shared__ int sh_l[256];
    int lmax = 1;
    for (int idx = threadIdx.x; idx < 2 * SUB_NO * T_NO; idx += blockDim.x) {
        int ch = idx / T_NO, tau_i = idx % T_NO;
        int s = ch >> 1, typ = ch & 1;
        float dly = expf(Delta_syn[ch]);
        float tt  = fmaxf((float)tau_i - dly, 0.0f) / expf(Tau_syn[ch]);
        float k   = tt * expf(-tt) * W_syn[ch];
        g_kern[typ * (SUB_NO * T_NO) + s * T_NO + tau_i] = k;
        if (fabsf(k) > 1e-12f) lmax = max(lmax, tau_i + 1);
    }
    sh_l[threadIdx.x] = lmax;
    __syncthreads();
    for (int off = 128; off > 0; off >>= 1) {
        if ((int)threadIdx.x < off)
            sh_l[threadIdx.x] = max(sh_l[threadIdx.x], sh_l[threadIdx.x + off]);
        __syncthreads();
    }
    if (threadIdx.x == 0) g_L = sh_l[0];
}

// ---------------- kernel 1: reparam + bf16 B tiles ----------------
__global__ void kern_reparam(const float* __restrict__ u_in, const float* __restrict__ v_in,
                             const float* __restrict__ C_log, float* __restrict__ out) {
    int col = blockIdx.x * blockDim.x + threadIdx.x;
    if (col >= NC) return;
    float cl[SUB_NO], th[SUB_NO], rz[SUB_NO];
    float m = -INFINITY;
#pragma unroll
    for (int s = 0; s < SUB_NO; s++) { cl[s] = C_log[s * NC + col]; m = fmaxf(m, cl[s]); }
    float sum = 0.0f;
#pragma unroll
    for (int s = 0; s < SUB_NO; s++) { th[s] = expf(cl[s] - m); sum += th[s]; }
    float inv = 1.0f / sum;
    int kidx = 0; float best = -INFINITY;
#pragma unroll
    for (int s = 0; s < SUB_NO; s++) {
        th[s] *= inv;
        float uu = u_in[s * NC + col];
        rz[s] = logf(th[s]) - logf(-logf(uu));
        if (rz[s] > best) { best = rz[s]; kidx = s; }
    }
    float nlvk = -logf(v_in[kidx * NC + col]);

    int chunk = col >> 6, kk = col & 63;
    __nv_bfloat16* tile = g_WbT + (size_t)chunk * 8192;
    int nbase = (col < E_NO) ? 0 : 64;

#pragma unroll
    for (int s = 0; s < SUB_NO; s++) {
        float hard = (s == kidx) ? 1.0f : 0.0f;
        float soft = 1.0f / (1.0f + expf(-2.0f * rz[s])) + 1e-9f;
        float nlv  = -logf(v_in[s * NC + col]);
        float rzb  = (s == kidx) ? (-logf(nlv)) : (-logf(nlv / th[s] + nlvk));
        float szb  = 1.0f / (1.0f + expf(-2.0f * rzb)) + 1e-9f;

        out[3 * T_DATA + 0 * SUB_NO * NC + s * NC + col] = th[s];
        out[3 * T_DATA + 1 * SUB_NO * NC + s * NC + col] = hard;
        out[3 * T_DATA + 2 * SUB_NO * NC + s * NC + col] = soft;
        out[3 * T_DATA + 3 * SUB_NO * NC + s * NC + col] = szb;

        float w3[3] = {hard, soft, szb};
#pragma unroll
        for (int var = 0; var < 3; var++) {
            uint32_t off = (uint32_t)((nbase + var * SUB_NO + s) * 128 + kk * 2);
            off ^= (off >> 3) & 0x70;
            tile[off >> 1] = __float2bfloat16_rn(w3[var]);
        }
    }
}

// ---------------- kernel 2: pipelined bf16 HMMA GEMM ----------------
// Block 64(M)x128(N), 256 thr = 8 warps (2M x 4N), warp tile 32x32.
// N cols 0-63 e-side, 64-127 i-side. Single smem buffer + register prefetch:
// LDGs for chunk c+1 issue before chunk c's mma; scoreboard wait lands at the
// next store, after ~1-2k cycles of tensor work.
__device__ __forceinline__ void gemm_loadA(float4* areg, const float* __restrict__ S_e,
                                           const float* __restrict__ S_i, int t0, int c, int tid) {
    int kc0 = c << 6;
#pragma unroll
    for (int j = 0; j < 4; j++) {
        int idx = tid + (j << 8);
        int r = idx >> 4, q = idx & 15;
        int t = t0 + r, k = kc0 + (q << 2);
        float4 val = make_float4(0.f, 0.f, 0.f, 0.f);
        if (t < T_DATA && k < NC)
            val = (k < E_NO) ? *(const float4*)(S_e + (size_t)t * E_NO + k)
                             : *(const float4*)(S_i + (size_t)t * I_NO + (k - E_NO));
        areg[j] = val;
    }
}

__global__ __launch_bounds__(256, 2) void kern_gemm(const float* __restrict__ S_e,
                                                    const float* __restrict__ S_i) {
    __shared__ __align__(1024) char As[8192];    // 64 rows x 128B (64 bf16), SW128
    __shared__ __align__(1024) char Bs[16384];   // 128 n-rows x 128B, SW128

    int tid  = threadIdx.x;
    int lane = tid & 31, warp = tid >> 5;
    int wm   = warp & 1, wn = warp >> 1;        // wm 0..1, wn 0..3
    int t0   = blockIdx.x * MT;

    uint32_t AsU = smem_u32(As), BsU = smem_u32(Bs);

    float acc[2][4][4];
#pragma unroll
    for (int ma = 0; ma < 2; ma++)
#pragma unroll
        for (int na = 0; na < 4; na++)
#pragma unroll
            for (int q = 0; q < 4; q++) acc[ma][na][q] = 0.0f;

    int aRow = wm * 32 + (lane & 15);
    int aByt = (lane >> 4) << 4;
    int bRow = wn * 32 + (lane & 7) + ((lane >> 4) << 3);
    int bByt = ((lane >> 3) & 1) << 4;

    float4 areg[4];
    uint4  breg[4];

    // prologue: prefetch chunk 0
    gemm_loadA(areg, S_e, S_i, t0, 0, tid);
    {
        const uint4* bs = (const uint4*)g_WbT;
#pragma unroll
        for (int j = 0; j < 4; j++) breg[j] = bs[tid + (j << 8)];
    }

    for (int c = 0; c < NCHUNK; c++) {
        __syncthreads();
        // store prefetched regs -> smem (cvt for A)
#pragma unroll
        for (int j = 0; j < 4; j++) {
            int idx = tid + (j << 8);
            int r = idx >> 4, q = idx & 15;
            uint32_t lo, hi;
            asm("cvt.rn.bf16x2.f32 %0, %1, %2;" : "=r"(lo) : "f"(areg[j].y), "f"(areg[j].x));
            asm("cvt.rn.bf16x2.f32 %0, %1, %2;" : "=r"(hi) : "f"(areg[j].w), "f"(areg[j].z));
            uint32_t off = (uint32_t)((r << 7) + (q << 3));
            off ^= (off >> 3) & 0x70;
            *(uint2*)(As + off) = make_uint2(lo, hi);
        }
        {
            uint4* bd = (uint4*)Bs;
#pragma unroll
            for (int j = 0; j < 4; j++) bd[tid + (j << 8)] = breg[j];
        }
        __syncthreads();

        // issue prefetch for chunk c+1 (no consumer until next store)
        if (c + 1 < NCHUNK) {
            gemm_loadA(areg, S_e, S_i, t0, c + 1, tid);
            const uint4* bs = (const uint4*)(g_WbT + (size_t)(c + 1) * 8192);
#pragma unroll
            for (int j = 0; j < 4; j++) breg[j] = bs[tid + (j << 8)];
        }

        // tensor work on current chunk
#pragma unroll
        for (int ks = 0; ks < 4; ks++) {
            uint32_t a[2][4], bf[8];
#pragma unroll
            for (int ma = 0; ma < 2; ma++) {
                int byt = (ks << 5) + aByt;
                int row = aRow + ma * 16;
                uint32_t ad = AsU + (uint32_t)row * 128 + (uint32_t)(byt ^ ((row & 7) << 4));
                ldsm4(a[ma], ad);
            }
#pragma unroll
            for (int p = 0; p < 2; p++) {
                int byt = (ks << 5) + bByt;
                int row = bRow + p * 16;
                uint32_t bd2 = BsU + (uint32_t)row * 128 + (uint32_t)(byt ^ ((row & 7) << 4));
                ldsm4(&bf[p * 4], bd2);
            }
#pragma unroll
            for (int ma = 0; ma < 2; ma++)
#pragma unroll
                for (int na = 0; na < 4; na++)
                    mma16816(acc[ma][na], a[ma], &bf[na * 2]);
        }
    }

    // epilogue: direct stores to [col][t]
    float* base = (wn < 2) ? g_INTe : g_INTi;
    int cloc = (wn & 1) * 32;
#pragma unroll
    for (int ma = 0; ma < 2; ma++) {
        int t_lo = t0 + wm * 32 + ma * 16 + (lane >> 2);
        int t_hi = t_lo + 8;
#pragma unroll
        for (int na = 0; na < 4; na++) {
            int c0 = cloc + na * 8 + (lane & 3) * 2;
            float* p0 = base + (size_t)c0 * T_DATA;
            float* p1 = base + (size_t)(c0 + 1) * T_DATA;
            if (t_lo < T_DATA) { p0[t_lo] = acc[ma][na][0]; p1[t_lo] = acc[ma][na][1]; }
            if (t_hi < T_DATA) { p0[t_hi] = acc[ma][na][2]; p1[t_hi] = acc[ma][na][3]; }
        }
    }
}

// ---------------- kernel 3: truncated causal conv, 8 outputs/thread ----------------
#define CT    1024
#define CSLOT 155
__global__ __launch_bounds__(128) void kern_conv() {
    __shared__ float ke[208], ki[208];
    __shared__ float es[8 * CSLOT + 8], is_[8 * CSLOT + 8];

    int bx = blockIdx.x;
    int sid = bx % 60, tile = bx / 60;
    int t0 = tile * CT, s = sid % 20, tid = threadIdx.x;

    int L = (g_L + 7) & ~7;
    if (L > 208) L = 208;
    int nrows = CT + L - 1;

    for (int tau = tid; tau < L; tau += 128) {
        ke[tau] = (tau < T_NO) ? g_kern[s * T_NO + tau] : 0.0f;
        ki[tau] = (tau < T_NO) ? g_kern[SUB_NO * T_NO + s * T_NO + tau] : 0.0f;
    }
    const float* ge = g_INTe + (size_t)sid * T_DATA;
    const float* gi = g_INTi + (size_t)sid * T_DATA;
    float* esb = es + 8;
    float* isb = is_ + 8;
    int tb = t0 - (L - 1);
    for (int j = tid; j < nrows; j += 128) {
        int t = tb + j;
        float ev = 0.0f, iv = 0.0f;
        if (t >= 0 && t < T_DATA) { ev = ge[t]; iv = gi[t]; }
        int a = (j & 7) * CSLOT + (j >> 3);
        esb[a] = ev; isb[a] = iv;
    }
    __syncthreads();

    int p0 = tid * 8 + L - 1;
    float ae[8], ai[8], ew[8], iw[8];
#pragma unroll
    for (int r = 0; r < 8; r++) {
        ae[r] = 0.0f; ai[r] = 0.0f;
        int j = p0 + r;
        int a = (j & 7) * CSLOT + (j >> 3);
        ew[r] = esb[a]; iw[r] = isb[a];
    }
    int nblk = L >> 3;
    for (int tbk = 0; tbk < nblk; tbk++) {
#pragma unroll
        for (int tu = 0; tu < 8; tu++) {
            int tau = tbk * 8 + tu;
            float fe = ke[tau], fi = ki[tau];
#pragma unroll
            for (int r = 0; r < 8; r++) {
                ae[r] = fmaf(fe, ew[r], ae[r]);
                ai[r] = fmaf(fi, iw[r], ai[r]);
            }
            int j = p0 - tau - 1;
            int a = (j & 7) * CSLOT + (j >> 3);
#pragma unroll
            for (int r = 7; r > 0; r--) { ew[r] = ew[r - 1]; iw[r] = iw[r - 1]; }
            ew[0] = esb[a]; iw[0] = isb[a];
        }
    }

    float* so = g_syn + (size_t)sid * T_DATA;
    int tt = t0 + tid * 8;
    if (tt + 7 < T_DATA) {
        *(float4*)(so + tt)     = make_float4(ae[0]+ai[0], ae[1]+ai[1], ae[2]+ai[2], ae[3]+ai[3]);
        *(float4*)(so + tt + 4) = make_float4(ae[4]+ai[4], ae[5]+ai[5], ae[6]+ai[6], ae[7]+ai[7]);
    } else {
#pragma unroll
        for (int r = 0; r < 8; r++)
            if (tt + r < T_DATA) so[tt + r] = ae[r] + ai[r];
    }
}

// ---------------- kernel 4: subunit tree ----------------
__global__ __launch_bounds__(256) void kern_tree(const float* __restrict__ W_sub,
                                                 const float* __restrict__ V_o,
                                                 float* __restrict__ out) {
    int idx = blockIdx.x * blockDim.x + threadIdx.x;
    if (idx >= 3 * T_DATA) return;
    int v = idx / T_DATA, t = idx - v * T_DATA;

    float ws[SUB_NO];
#pragma unroll
    for (int s = 0; s < SUB_NO; s++) ws[s] = __ldg(&W_sub[s]);

    const float* sy = g_syn + (size_t)v * SUB_NO * T_DATA + t;
    float sub[SUB_NO];
#pragma unroll
    for (int ss = 0; ss < SUB_NO; ss++) {
        int s = SUB_NO - 1 - ss;
        float x = sy[(size_t)s * T_DATA];
        if (2 * s + 1 < SUB_NO) x += sub[2 * s + 1] * ws[2 * s + 1];
        if (2 * s + 2 < SUB_NO) x += sub[2 * s + 2] * ws[2 * s + 2];
        sub[s] = tanhf(x);
    }
    out[idx] = sub[0] * ws[0] + __ldg(&V_o[0]);
}

// ---------------- launcher ----------------
extern "C" void kernel_launch(void* const* d_in, const int* in_sizes, int n_in,
                              void* d_out, int out_size) {
    const float* S_e   = (const float*)d_in[0];
    const float* S_i   = (const float*)d_in[1];
    const float* u     = (const float*)d_in[2];
    const float* v     = (const float*)d_in[3];
    const float* W_syn = (const float*)d_in[4];
    const float* Tau   = (const float*)d_in[5];
    const float* Delta = (const float*)d_in[6];
    const float* W_sub = (const float*)d_in[7];
    const float* V_o   = (const float*)d_in[8];
    const float* C_log = (const float*)d_in[10];
    float* out = (float*)d_out;

    kern_setup<<<1, 256>>>(W_syn, Tau, Delta);
    kern_reparam<<<(NC + 255) / 256, 256>>>(u, v, C_log, out);
    kern_gemm<<<(T_DATA + MT - 1) / MT, 256>>>(S_e, S_i);
    kern_conv<<<60 * ((T_DATA + CT - 1) / CT), 128>>>();
    kern_tree<<<(3 * T_DATA + 255) / 256, 256>>>(W_sub, V_o, out);
}